// round 15
// baseline (speedup 1.0000x reference)
#include <cuda_runtime.h>
#include <cuda_bf16.h>

#define C      128
#define GRP    32
#define CPG    4
#define BMAX   64      // batch_size is 16; oversize scratch for safety
#define EPSF   1e-5f

// Scratch (no device allocation allowed -> __device__ globals)
__device__ float  g_sum[BMAX * C];
__device__ float  g_sq [BMAX * C];
__device__ float4 g_scale4[BMAX * GRP];
__device__ float4 g_shift4[BMAX * GRP];
__device__ int    g_start[BMAX + 2];

// ---------------------------------------------------------------------------
// Kernel A: segment boundaries via binary search on sorted batch_id,
//           plus zero the accumulators. 1 block, trivial cost.
// ---------------------------------------------------------------------------
__global__ void setup_kernel(const int* __restrict__ bid, int n) {
    int t = threadIdx.x;
    if (t <= BMAX) {
        int lo = 0, hi = n;
        while (lo < hi) {
            int mid = (lo + hi) >> 1;
            if (bid[mid] < t) lo = mid + 1; else hi = mid;
        }
        g_start[t] = lo;
    }
    for (int i = t; i < BMAX * C; i += blockDim.x) {
        g_sum[i] = 0.0f;
        g_sq[i]  = 0.0f;
    }
}

// ---------------------------------------------------------------------------
// Kernel B: per-(batch,channel) sum and sum-of-squares.
// Block = 256 threads: quad q = tid&31 owns channels [4q,4q+4), rowLane =
// tid>>5 strides rows by 8. Blocks own contiguous row chunks; the sorted
// segment table makes every inner loop batch-uniform. Register accumulation
// -> shared reduce -> few global atomics. Streaming loads, unroll 8 for MLP.
// ---------------------------------------------------------------------------
__global__ __launch_bounds__(256) void stats_kernel(const float4* __restrict__ data4, int n) {
    __shared__ int   ss[BMAX + 1];
    __shared__ float red[8][256];

    const int tid = threadIdx.x;
    const int q   = tid & 31;
    const int rl  = tid >> 5;

    for (int i = tid; i <= BMAX; i += 256) ss[i] = g_start[i];
    __syncthreads();

    const int chunk = (n + gridDim.x - 1) / gridDim.x;
    const int row0  = blockIdx.x * chunk;
    const int row1  = min(n, row0 + chunk);
    if (row0 >= row1) return;                      // uniform per block

    for (int b = 0; b < BMAX; ++b) {
        const int lo = max(row0, ss[b]);
        const int hi = min(row1, ss[b + 1]);
        if (lo >= hi) continue;                    // uniform per block

        float4 s1 = make_float4(0.f, 0.f, 0.f, 0.f);
        float4 s2 = make_float4(0.f, 0.f, 0.f, 0.f);

        const float4* p = data4 + (size_t)(lo + rl) * 32 + q;
        int r = lo + rl;
        #pragma unroll 8
        for (; r < hi; r += 8, p += 8 * 32) {
            float4 x = __ldcs(p);
            s1.x += x.x; s1.y += x.y; s1.z += x.z; s1.w += x.w;
            s2.x = fmaf(x.x, x.x, s2.x);
            s2.y = fmaf(x.y, x.y, s2.y);
            s2.z = fmaf(x.z, x.z, s2.z);
            s2.w = fmaf(x.w, x.w, s2.w);
        }

        // reduce across the 8 rowLanes
        const int base = q * 8;
        red[rl][base + 0] = s1.x; red[rl][base + 1] = s1.y;
        red[rl][base + 2] = s1.z; red[rl][base + 3] = s1.w;
        red[rl][base + 4] = s2.x; red[rl][base + 5] = s2.y;
        red[rl][base + 6] = s2.z; red[rl][base + 7] = s2.w;
        __syncthreads();

        float v = 0.0f;
        #pragma unroll
        for (int w = 0; w < 8; ++w) v += red[w][tid];

        const int q2 = tid >> 3;        // quad index 0..31
        const int j  = tid & 7;         // 0..3 => sum, 4..7 => sumsq
        const int c  = q2 * 4 + (j & 3);
        if (j < 4) atomicAdd(&g_sum[b * C + c], v);
        else       atomicAdd(&g_sq [b * C + c], v);
        __syncthreads();
    }
}

// ---------------------------------------------------------------------------
// Kernel C: per-(batch,group) stats -> per-channel scale/shift table.
//   m   = S1g * ic,  ic = 1/(count*CPG + eps)
//   var = ic*S2g - m^2*(2 - K*ic)     (exact rewrite of reference's 2-pass)
// ---------------------------------------------------------------------------
__global__ void finalize_kernel(const float* __restrict__ w, const float* __restrict__ bias) {
    int tid = blockIdx.x * blockDim.x + threadIdx.x;
    if (tid >= BMAX * GRP) return;
    int b = tid >> 5;
    int g = tid & 31;

    int   cnt = g_start[b + 1] - g_start[b];
    float K   = (float)cnt * (float)CPG;
    float ic  = 1.0f / (K + EPSF);

    int cb = b * C + g * 4;
    float S1 = g_sum[cb] + g_sum[cb + 1] + g_sum[cb + 2] + g_sum[cb + 3];
    float S2 = g_sq [cb] + g_sq [cb + 1] + g_sq [cb + 2] + g_sq [cb + 3];

    float m    = S1 * ic;
    float var  = S2 * ic - m * m * (2.0f - K * ic);
    float istd = 1.0f / sqrtf(var + EPSF);

    int c0 = g * 4;
    float4 sc, sh;
    sc.x = istd * w[c0 + 0];  sh.x = bias[c0 + 0] - m * sc.x;
    sc.y = istd * w[c0 + 1];  sh.y = bias[c0 + 1] - m * sc.y;
    sc.z = istd * w[c0 + 2];  sh.z = bias[c0 + 2] - m * sc.z;
    sc.w = istd * w[c0 + 3];  sh.w = bias[c0 + 3] - m * sc.w;

    g_scale4[b * GRP + g] = sc;
    g_shift4[b * GRP + g] = sh;
}

// ---------------------------------------------------------------------------
// Kernel D: out = x * scale[b][c] + shift[b][c].
// Segment-chunked: blocks own contiguous row ranges; within a segment, b is
// loop-invariant and (stride 256 % 32 == 0) each thread's quad q is constant,
// so scale/shift live in registers. Inner loop = LDG.128 + 4 FMA + STG.128.
// No bid reads, no per-element table gathers.
// ---------------------------------------------------------------------------
__global__ __launch_bounds__(256) void apply_kernel(const float4* __restrict__ data4,
                                                    float4*       __restrict__ out4,
                                                    int n) {
    __shared__ int ss[BMAX + 1];
    const int tid = threadIdx.x;
    for (int i = tid; i <= BMAX; i += 256) ss[i] = g_start[i];
    __syncthreads();

    const int chunk = (n + gridDim.x - 1) / gridDim.x;
    const int row0  = blockIdx.x * chunk;
    const int row1  = min(n, row0 + chunk);
    if (row0 >= row1) return;                      // uniform per block

    const int q = tid & 31;

    for (int b = 0; b < BMAX; ++b) {
        const int lo = max(row0, ss[b]);
        const int hi = min(row1, ss[b + 1]);
        if (lo >= hi) continue;                    // uniform per block

        const float4 sc = g_scale4[b * GRP + q];   // loop-invariant registers
        const float4 sh = g_shift4[b * GRP + q];

        const int j1 = hi * 32;
        for (int j = lo * 32 + tid; j < j1; j += 256) {
            float4 x = __ldcs(data4 + j);
            float4 o;
            o.x = fmaf(x.x, sc.x, sh.x);
            o.y = fmaf(x.y, sc.y, sh.y);
            o.z = fmaf(x.z, sc.z, sh.z);
            o.w = fmaf(x.w, sc.w, sh.w);
            __stcs(out4 + j, o);
        }
    }
}

// ---------------------------------------------------------------------------
// inputs (metadata order): data[N*128] f32, weights[128] f32, bias[128] f32,
//                          batch_id[N] i32, batch_size[1] i32
// output: [N*128] f32
// ---------------------------------------------------------------------------
extern "C" void kernel_launch(void* const* d_in, const int* in_sizes, int n_in,
                              void* d_out, int out_size) {
    const float* data = (const float*)d_in[0];
    const float* w    = (const float*)d_in[1];
    const float* bias = (const float*)d_in[2];
    const int*   bid  = (const int*)d_in[3];
    const int n = in_sizes[3];

    setup_kernel<<<1, 128>>>(bid, n);

    int sblocks = 148 * 8;                       // full residency, contiguous chunks
    stats_kernel<<<sblocks, 256>>>((const float4*)data, n);

    finalize_kernel<<<(BMAX * GRP + 255) / 256, 256>>>(w, bias);

    int ablocks = 148 * 8;                       // one wave, chunked rows
    apply_kernel<<<ablocks, 256>>>((const float4*)data, (float4*)d_out, n);
}

// round 16
// speedup vs baseline: 1.0169x; 1.0169x over previous
#include <cuda_runtime.h>
#include <cuda_bf16.h>

#define C      128
#define GRP    32
#define CPG    4
#define BMAX   64      // batch_size is 16; oversize scratch for safety
#define EPSF   1e-5f

// Scratch (no device allocation allowed -> __device__ globals)
__device__ float  g_sum[BMAX * C];
__device__ float  g_sq [BMAX * C];
__device__ float4 g_scale4[BMAX * GRP];
__device__ float4 g_shift4[BMAX * GRP];
__device__ int    g_start[BMAX + 2];

// ---------------------------------------------------------------------------
// Kernel A: segment boundaries via binary search on sorted batch_id,
//           plus zero the accumulators. 1 block, trivial cost.
// ---------------------------------------------------------------------------
__global__ void setup_kernel(const int* __restrict__ bid, int n) {
    int t = threadIdx.x;
    if (t <= BMAX) {
        int lo = 0, hi = n;
        while (lo < hi) {
            int mid = (lo + hi) >> 1;
            if (bid[mid] < t) lo = mid + 1; else hi = mid;
        }
        g_start[t] = lo;
    }
    for (int i = t; i < BMAX * C; i += blockDim.x) {
        g_sum[i] = 0.0f;
        g_sq[i]  = 0.0f;
    }
}

// ---------------------------------------------------------------------------
// Kernel B: per-(batch,channel) sum and sum-of-squares.
// Block = 256 threads: quad q = tid&31 owns channels [4q,4q+4), rowLane =
// tid>>5 strides rows by 8. Blocks own contiguous row chunks; the sorted
// segment table makes every inner loop batch-uniform. Register accumulation
// -> shared reduce -> few global atomics. Streaming loads, unroll 8 for MLP.
// (unroll 8 measured: ~12us faster than unroll 4 in R15)
// ---------------------------------------------------------------------------
__global__ __launch_bounds__(256) void stats_kernel(const float4* __restrict__ data4, int n) {
    __shared__ int   ss[BMAX + 1];
    __shared__ float red[8][256];

    const int tid = threadIdx.x;
    const int q   = tid & 31;
    const int rl  = tid >> 5;

    for (int i = tid; i <= BMAX; i += 256) ss[i] = g_start[i];
    __syncthreads();

    const int chunk = (n + gridDim.x - 1) / gridDim.x;
    const int row0  = blockIdx.x * chunk;
    const int row1  = min(n, row0 + chunk);
    if (row0 >= row1) return;                      // uniform per block

    for (int b = 0; b < BMAX; ++b) {
        const int lo = max(row0, ss[b]);
        const int hi = min(row1, ss[b + 1]);
        if (lo >= hi) continue;                    // uniform per block

        float4 s1 = make_float4(0.f, 0.f, 0.f, 0.f);
        float4 s2 = make_float4(0.f, 0.f, 0.f, 0.f);

        const float4* p = data4 + (size_t)(lo + rl) * 32 + q;
        int r = lo + rl;
        #pragma unroll 8
        for (; r < hi; r += 8, p += 8 * 32) {
            float4 x = __ldcs(p);
            s1.x += x.x; s1.y += x.y; s1.z += x.z; s1.w += x.w;
            s2.x = fmaf(x.x, x.x, s2.x);
            s2.y = fmaf(x.y, x.y, s2.y);
            s2.z = fmaf(x.z, x.z, s2.z);
            s2.w = fmaf(x.w, x.w, s2.w);
        }

        // reduce across the 8 rowLanes
        const int base = q * 8;
        red[rl][base + 0] = s1.x; red[rl][base + 1] = s1.y;
        red[rl][base + 2] = s1.z; red[rl][base + 3] = s1.w;
        red[rl][base + 4] = s2.x; red[rl][base + 5] = s2.y;
        red[rl][base + 6] = s2.z; red[rl][base + 7] = s2.w;
        __syncthreads();

        float v = 0.0f;
        #pragma unroll
        for (int w = 0; w < 8; ++w) v += red[w][tid];

        const int q2 = tid >> 3;        // quad index 0..31
        const int j  = tid & 7;         // 0..3 => sum, 4..7 => sumsq
        const int c  = q2 * 4 + (j & 3);
        if (j < 4) atomicAdd(&g_sum[b * C + c], v);
        else       atomicAdd(&g_sq [b * C + c], v);
        __syncthreads();
    }
}

// ---------------------------------------------------------------------------
// Kernel C: per-(batch,group) stats -> per-channel scale/shift table.
//   m   = S1g * ic,  ic = 1/(count*CPG + eps)
//   var = ic*S2g - m^2*(2 - K*ic)     (exact rewrite of reference's 2-pass)
// ---------------------------------------------------------------------------
__global__ void finalize_kernel(const float* __restrict__ w, const float* __restrict__ bias) {
    int tid = blockIdx.x * blockDim.x + threadIdx.x;
    if (tid >= BMAX * GRP) return;
    int b = tid >> 5;
    int g = tid & 31;

    int   cnt = g_start[b + 1] - g_start[b];
    float K   = (float)cnt * (float)CPG;
    float ic  = 1.0f / (K + EPSF);

    int cb = b * C + g * 4;
    float S1 = g_sum[cb] + g_sum[cb + 1] + g_sum[cb + 2] + g_sum[cb + 3];
    float S2 = g_sq [cb] + g_sq [cb + 1] + g_sq [cb + 2] + g_sq [cb + 3];

    float m    = S1 * ic;
    float var  = S2 * ic - m * m * (2.0f - K * ic);
    float istd = 1.0f / sqrtf(var + EPSF);

    int c0 = g * 4;
    float4 sc, sh;
    sc.x = istd * w[c0 + 0];  sh.x = bias[c0 + 0] - m * sc.x;
    sc.y = istd * w[c0 + 1];  sh.y = bias[c0 + 1] - m * sc.y;
    sc.z = istd * w[c0 + 2];  sh.z = bias[c0 + 2] - m * sc.z;
    sc.w = istd * w[c0 + 3];  sh.w = bias[c0 + 3] - m * sc.w;

    g_scale4[b * GRP + g] = sc;
    g_shift4[b * GRP + g] = sh;
}

// ---------------------------------------------------------------------------
// Kernel D: out = x * scale[b][c] + shift[b][c]. Grid-stride, 1 ld + 1 st
// per iteration (the measured winner: 299.9us, DRAM 84.2%, occ 95%).
// Multi-wave short blocks self-balance; per-element bid load is latency-
// covered. int32 indexing (total = n*32 = 64M < 2^31).
// ---------------------------------------------------------------------------
__global__ __launch_bounds__(256) void apply_kernel(const float4* __restrict__ data4,
                                                    const int*    __restrict__ bid,
                                                    float4*       __restrict__ out4,
                                                    int total) {
    const int stride = gridDim.x * blockDim.x;
    for (int i = blockIdx.x * blockDim.x + threadIdx.x; i < total; i += stride) {
        int r = i >> 5;            // row
        int q = i & 31;            // quad-of-channels within row
        int b = __ldg(&bid[r]);    // warp-uniform broadcast load
        float4 x  = __ldcs(&data4[i]);
        float4 sc = g_scale4[b * GRP + q];
        float4 sh = g_shift4[b * GRP + q];
        float4 o;
        o.x = fmaf(x.x, sc.x, sh.x);
        o.y = fmaf(x.y, sc.y, sh.y);
        o.z = fmaf(x.z, sc.z, sh.z);
        o.w = fmaf(x.w, sc.w, sh.w);
        __stcs(&out4[i], o);
    }
}

// ---------------------------------------------------------------------------
// inputs (metadata order): data[N*128] f32, weights[128] f32, bias[128] f32,
//                          batch_id[N] i32, batch_size[1] i32
// output: [N*128] f32
// ---------------------------------------------------------------------------
extern "C" void kernel_launch(void* const* d_in, const int* in_sizes, int n_in,
                              void* d_out, int out_size) {
    const float* data = (const float*)d_in[0];
    const float* w    = (const float*)d_in[1];
    const float* bias = (const float*)d_in[2];
    const int*   bid  = (const int*)d_in[3];
    const int n = in_sizes[3];

    setup_kernel<<<1, 128>>>(bid, n);

    int sblocks = 148 * 8;                       // full residency, contiguous chunks
    stats_kernel<<<sblocks, 256>>>((const float4*)data, n);

    finalize_kernel<<<(BMAX * GRP + 255) / 256, 256>>>(w, bias);

    int total   = n * 32;                        // 64M float4, fits int32
    int ablocks = min(148 * 32, (total + 255) / 256);
    apply_kernel<<<ablocks, 256>>>((const float4*)data, bid, (float4*)d_out, total);
}